// round 15
// baseline (speedup 1.0000x reference)

#include <cuda_runtime.h>
#include <cuda_bf16.h>
#include <mma.h>
#include <cstdint>
#include <cstddef>
#include <type_traits>

using namespace nvcuda;

#define BATCH 8
#define CCH   512
#define NPIX  4096
#define CQD   64

// ---------------- static scratch (no runtime allocation allowed) ----------------
__device__ __nv_bfloat16 g_xb[(size_t)BATCH * CCH * NPIX];       // x in bf16
__device__ __nv_bfloat16 g_Wqk[2 * CQD * CCH];                   // [Wq; Wk]
__device__ float         g_bqk[2 * CQD];                         // [bq; bk]
__device__ __nv_bfloat16 g_Wv[CCH * CCH];
__device__ __nv_bfloat16 g_qk[(size_t)BATCH * 2 * CQD * NPIX];   // q rows 0-63, k rows 64-127
__device__ __nv_bfloat16 g_v[(size_t)BATCH * CCH * NPIX];
__device__ __nv_bfloat16 g_attn[(size_t)BATCH * NPIX * NPIX];    // exp(scores), unnormalized
__device__ float         g_rspart[(size_t)BATCH * 4 * NPIX];     // per-jgroup rowsum partials

// ---------------- helpers ----------------
__device__ __forceinline__ uint32_t smem_u32(const void* p) {
    uint32_t a;
    asm("{ .reg .u64 t; cvta.to.shared.u64 t, %1; cvt.u32.u64 %0, t; }" : "=r"(a) : "l"(p));
    return a;
}
__device__ __forceinline__ void cpa16(uint32_t dst, const void* src) {
    asm volatile("cp.async.cg.shared.global [%0], [%1], 16;" :: "r"(dst), "l"(src));
}
#define CP_COMMIT() asm volatile("cp.async.commit_group;" ::: "memory")
#define CP_WAIT(n)  asm volatile("cp.async.wait_group %0;" :: "n"(n) : "memory")

// ---------------- fp32 -> bf16 cast (vectorized) ----------------
__global__ void cast_kernel(const float* __restrict__ in,
                            __nv_bfloat16* __restrict__ out, size_t n4) {
    size_t i = (size_t)blockIdx.x * blockDim.x + threadIdx.x;
    if (i < n4) {
        float4 f = reinterpret_cast<const float4*>(in)[i];
        __nv_bfloat162 a = __floats2bfloat162_rn(f.x, f.y);
        __nv_bfloat162 b = __floats2bfloat162_rn(f.z, f.w);
        uint2 u;
        u.x = *reinterpret_cast<unsigned*>(&a);
        u.y = *reinterpret_cast<unsigned*>(&b);
        reinterpret_cast<uint2*>(out)[i] = u;
    }
}

// ---------------- bias concat ----------------
__global__ void concat_bias(const float* __restrict__ bq, const float* __restrict__ bk,
                            float* __restrict__ bqk) {
    int t = threadIdx.x;
    bqk[t] = (t < CQD) ? bq[t] : bk[t - CQD];
}

// ============ scores kernel: Q-resident, 8 pipelined j-tiles, register rowsum ============
// attn[i,j] = exp(sum_d q[d,i]*k[d,j]).  128 threads, 4 warps of 64x64.
// Each CTA covers 128 i-rows x 1024 j-cols (jg in 0..3).
__global__ void __launch_bounds__(128, 2)
scores_pipe(const __nv_bfloat16* __restrict__ qk,
            __nv_bfloat16* __restrict__ attn, float* __restrict__ rspart)
{
    constexpr int LDS = 136;                 // 128 + 8 pad (halves)
    constexpr int TILE = 64 * LDS;
    extern __shared__ char dsm[];
    __nv_bfloat16* smA = reinterpret_cast<__nv_bfloat16*>(dsm);     // [64][136]
    __nv_bfloat16* smB = smA + TILE;                                // 2 x [64][136]
    float* stage = reinterpret_cast<float*>(smB + 2 * TILE);        // [4][256]
    float* auxRS = stage + 4 * 256;                                 // [2][128]
    const uint32_t smA_u = smem_u32(smA);
    const uint32_t smB_u = smem_u32(smB);

    const int b = blockIdx.z;
    const int jg = blockIdx.x;               // 0..3, j in [jg*1024, jg*1024+1024)
    const int i0 = blockIdx.y * 128;
    const int tid = threadIdx.x;
    const int wid = tid >> 5, lane = tid & 31;
    const int wm0 = (wid & 1) * 64;
    const int wn0 = (wid >> 1) * 64;

    const __nv_bfloat16* qb = qk + (size_t)b * (2 * CQD) * NPIX;
    const __nv_bfloat16* kb = qb + (size_t)CQD * NPIX;
    __nv_bfloat16* attnb = attn + (size_t)b * NPIX * NPIX;

    float part[4][4];
#pragma unroll
    for (int i = 0; i < 4; i++)
#pragma unroll
        for (int p = 0; p < 4; p++) part[i][p] = 0.0f;

    // prologue: A (q block, resident) + B(j-tile 0)
#pragma unroll
    for (int it = 0; it < 8; ++it) {
        int idx = tid + it * 128;
        int r = idx >> 4, cv = idx & 15;
        cpa16(smA_u + (uint32_t)(r * LDS + cv * 8) * 2,
              qb + (size_t)r * NPIX + i0 + cv * 8);
    }
    {
        const int j0 = jg * 1024;
#pragma unroll
        for (int it = 0; it < 8; ++it) {
            int idx = tid + it * 128;
            int r = idx >> 4, cv = idx & 15;
            cpa16(smB_u + (uint32_t)(r * LDS + cv * 8) * 2,
                  kb + (size_t)r * NPIX + j0 + cv * 8);
        }
    }
    CP_COMMIT();

    for (int jt = 0; jt < 8; ++jt) {
        const int cur = jt & 1;
        if (jt + 1 < 8) {
            const int j0 = jg * 1024 + (jt + 1) * 128;
            const uint32_t bbuf = smB_u + (uint32_t)((cur ^ 1) * TILE) * 2;
#pragma unroll
            for (int it = 0; it < 8; ++it) {
                int idx = tid + it * 128;
                int r = idx >> 4, cv = idx & 15;
                cpa16(bbuf + (uint32_t)(r * LDS + cv * 8) * 2,
                      kb + (size_t)r * NPIX + j0 + cv * 8);
            }
            CP_COMMIT();
            CP_WAIT(1);
        } else {
            CP_WAIT(0);
        }
        __syncthreads();

        // MMA: S(128x128) = A^T * B over K=64
        wmma::fragment<wmma::accumulator, 16, 16, 16, float> acc[4][4];
#pragma unroll
        for (int i = 0; i < 4; i++)
#pragma unroll
            for (int j = 0; j < 4; j++) wmma::fill_fragment(acc[i][j], 0.0f);

        const __nv_bfloat16* b0 = smB + cur * TILE;
#pragma unroll
        for (int kk = 0; kk < 64; kk += 16) {
            wmma::fragment<wmma::matrix_a, 16, 16, 16, __nv_bfloat16, wmma::col_major> af[4];
            wmma::fragment<wmma::matrix_b, 16, 16, 16, __nv_bfloat16, wmma::row_major> bfr[4];
#pragma unroll
            for (int i = 0; i < 4; i++)
                wmma::load_matrix_sync(af[i], smA + kk * LDS + wm0 + i * 16, LDS);
#pragma unroll
            for (int j = 0; j < 4; j++)
                wmma::load_matrix_sync(bfr[j], b0 + kk * LDS + wn0 + j * 16, LDS);
#pragma unroll
            for (int i = 0; i < 4; i++)
#pragma unroll
                for (int j = 0; j < 4; j++)
                    wmma::mma_sync(acc[i][j], af[i], bfr[j], acc[i][j]);
        }
        __syncthreads();

        // epilogue: exp -> attn (bf16x2 stores), register rowsum partials
        const int jbase = jg * 1024 + jt * 128;
#pragma unroll
        for (int i = 0; i < 4; i++) {
#pragma unroll
            for (int j = 0; j < 4; j++) {
                wmma::store_matrix_sync(&stage[wid * 256], acc[i][j], 16, wmma::mem_row_major);
                __syncwarp();
                int rowBase = i0 + wm0 + i * 16;
                int colBase = jbase + wn0 + j * 16;
#pragma unroll
                for (int p = 0; p < 4; ++p) {
                    int pi = lane + 32 * p;          // pair index 0..127
                    int r = pi >> 3, c = (pi & 7) * 2;
                    float e0 = __expf(stage[wid * 256 + r * 16 + c]);
                    float e1 = __expf(stage[wid * 256 + r * 16 + c + 1]);
                    part[i][p] += e0 + e1;
                    __nv_bfloat162 h = __floats2bfloat162_rn(e0, e1);
                    *reinterpret_cast<uint32_t*>(
                        &attnb[(size_t)(rowBase + r) * NPIX + colBase + c]) =
                        *reinterpret_cast<uint32_t*>(&h);
                }
                __syncwarp();
            }
        }
        __syncthreads();
    }

    // end-of-kernel rowsum reduction: 8-lane groups share a row
#pragma unroll
    for (int i = 0; i < 4; i++) {
#pragma unroll
        for (int p = 0; p < 4; p++) {
            float s = part[i][p];
            s += __shfl_xor_sync(0xffffffffu, s, 1);
            s += __shfl_xor_sync(0xffffffffu, s, 2);
            s += __shfl_xor_sync(0xffffffffu, s, 4);
            if ((lane & 7) == 0)
                auxRS[(wid >> 1) * 128 + wm0 + i * 16 + (lane >> 3) + 4 * p] = s;
        }
    }
    __syncthreads();
    rspart[((size_t)b * 4 + jg) * NPIX + i0 + tid] = auxRS[tid] + auxRS[128 + tid];
}
static constexpr size_t SCORES_SMEM =
    (size_t)3 * 64 * 136 * 2 + 4 * 256 * 4 + 2 * 128 * 4 + 128;

// ============ 3-stage pipelined 128x128 GEMM: cp.async, 4 warps of 64x64 ============
// EPI 1: bf16 (acc + bias[row])
// EPI 2: fp32 (gamma/rowsum[col]*acc + xres), rowsum = sum of 4 rspart groups
// Epilogue stage/aux scratch ALIASED onto stage-0 buffer (valid post-mainloop).
template<bool AROW, bool BROW, int EPI>
__global__ void __launch_bounds__(128, 2)
gemm_pipe(const __nv_bfloat16* __restrict__ A, size_t strideA, int lda,
          const __nv_bfloat16* __restrict__ Bm, size_t strideB, int ldb,
          void* __restrict__ Cm, size_t strideC, int ldc,
          const float* __restrict__ bias,
          const float* __restrict__ gamma,
          const float* __restrict__ xres, size_t strideX,
          const float* __restrict__ rspart,
          int M, int N, int K)
{
    constexpr int BM = 128, BN = 128, BK = 64, WM = 64, WN = 64;
    constexpr int WGM = BM / WM;
    constexpr int MI = WM / 16, NI = WN / 16;
    constexpr int SA_R = AROW ? BM : BK, SA_C = AROW ? BK : BM;
    constexpr int SB_R = BROW ? BK : BN, SB_C = BROW ? BN : BK;
    constexpr int LDA_S = SA_C + 8, LDB_S = SB_C + 8;
    constexpr int AELEM = SA_R * LDA_S;
    constexpr int BELEM = SB_R * LDB_S;
    constexpr int CVA = SA_C / 8, CVB = SB_C / 8;
    constexpr int ITA = (SA_R * CVA) / 128;
    constexpr int ITB = (SB_R * CVB) / 128;

    extern __shared__ char dsm[];
    __nv_bfloat16* smA = reinterpret_cast<__nv_bfloat16*>(dsm);   // 3 stages
    __nv_bfloat16* smB = smA + 3 * AELEM;                         // 3 stages
    // epilogue scratch aliased over stage-0 (used only after final sync)
    float* stage = reinterpret_cast<float*>(dsm);                 // [4][256]
    float* aux = stage + 4 * 256;                                 // [128]
    const uint32_t smA_u = smem_u32(smA);
    const uint32_t smB_u = smem_u32(smB);

    const int b = blockIdx.z;
    const __nv_bfloat16* Ab = A + strideA * (size_t)b;
    const __nv_bfloat16* Bb = Bm + strideB * (size_t)b;
    const size_t cb = strideC * (size_t)b;

    const int blockM = blockIdx.y * BM;
    const int blockN = blockIdx.x * BN;
    const int tid = threadIdx.x;
    const int wid = tid >> 5, lane = tid & 31;
    const int wm0 = (wid % WGM) * WM;
    const int wn0 = (wid / WGM) * WN;

    using ALayout = typename std::conditional<AROW, wmma::row_major, wmma::col_major>::type;
    using BLayout = typename std::conditional<BROW, wmma::row_major, wmma::col_major>::type;

    wmma::fragment<wmma::accumulator, 16, 16, 16, float> acc[MI][NI];
#pragma unroll
    for (int i = 0; i < MI; i++)
#pragma unroll
        for (int j = 0; j < NI; j++) wmma::fill_fragment(acc[i][j], 0.0f);

    auto loadA = [&](int buf, int k0) {
#pragma unroll
        for (int it = 0; it < ITA; ++it) {
            int idx = tid + it * 128;
            int r = idx / CVA, cv = idx % CVA;
            const __nv_bfloat16* src = AROW
                ? Ab + (size_t)(blockM + r) * lda + k0 + cv * 8
                : Ab + (size_t)(k0 + r) * lda + blockM + cv * 8;
            cpa16(smA_u + (uint32_t)(buf * AELEM + r * LDA_S + cv * 8) * 2, src);
        }
    };
    auto loadB = [&](int buf, int k0) {
#pragma unroll
        for (int it = 0; it < ITB; ++it) {
            int idx = tid + it * 128;
            int r = idx / CVB, cv = idx % CVB;
            const __nv_bfloat16* src = BROW
                ? Bb + (size_t)(k0 + r) * ldb + blockN + cv * 8
                : Bb + (size_t)(blockN + r) * ldb + k0 + cv * 8;
            cpa16(smB_u + (uint32_t)(buf * BELEM + r * LDB_S + cv * 8) * 2, src);
        }
    };

    const int T = K / BK;
    loadA(0, 0); loadB(0, 0); CP_COMMIT();
    if (T > 1) { loadA(1, BK); loadB(1, BK); CP_COMMIT(); }

    for (int t = 0; t < T; ++t) {
        const int cur = t % 3;
        if (t + 1 < T) { CP_WAIT(1); } else { CP_WAIT(0); }
        __syncthreads();

        const __nv_bfloat16* a0 = smA + cur * AELEM;
        const __nv_bfloat16* b0 = smB + cur * BELEM;
#pragma unroll
        for (int kk = 0; kk < BK; kk += 16) {
            wmma::fragment<wmma::matrix_a, 16, 16, 16, __nv_bfloat16, ALayout> af[MI];
            wmma::fragment<wmma::matrix_b, 16, 16, 16, __nv_bfloat16, BLayout> bfr[NI];
#pragma unroll
            for (int i = 0; i < MI; i++) {
                const __nv_bfloat16* p = AROW ? a0 + (wm0 + i * 16) * LDA_S + kk
                                              : a0 + kk * LDA_S + wm0 + i * 16;
                wmma::load_matrix_sync(af[i], p, LDA_S);
            }
#pragma unroll
            for (int j = 0; j < NI; j++) {
                const __nv_bfloat16* p = BROW ? b0 + kk * LDB_S + wn0 + j * 16
                                              : b0 + (wn0 + j * 16) * LDB_S + kk;
                wmma::load_matrix_sync(bfr[j], p, LDB_S);
            }
#pragma unroll
            for (int i = 0; i < MI; i++)
#pragma unroll
                for (int j = 0; j < NI; j++)
                    wmma::mma_sync(acc[i][j], af[i], bfr[j], acc[i][j]);
        }
        __syncthreads();

        if (t + 2 < T) {
            loadA((t + 2) % 3, (t + 2) * BK);
            loadB((t + 2) % 3, (t + 2) * BK);
            CP_COMMIT();
        }
    }

    // ---- epilogue (scratch aliased over stage-0; all loads/MMAs complete) ----
    if (EPI == 2) {
        float rs = 0.0f;
#pragma unroll
        for (int jg = 0; jg < 4; ++jg)
            rs += rspart[((size_t)b * 4 + jg) * NPIX + blockN + tid];
        aux[tid] = gamma[0] / rs;
        __syncthreads();
    }

#pragma unroll
    for (int i = 0; i < MI; i++) {
#pragma unroll
        for (int j = 0; j < NI; j++) {
            wmma::store_matrix_sync(&stage[wid * 256], acc[i][j], 16, wmma::mem_row_major);
            __syncwarp();
            int rowBase = blockM + wm0 + i * 16;
            int colBase = blockN + wn0 + j * 16;
#pragma unroll
            for (int e = lane; e < 256; e += 32) {
                int r = e >> 4, c = e & 15;
                float val = stage[wid * 256 + e];
                size_t o = (size_t)(rowBase + r) * ldc + colBase + c;
                if (EPI == 1) {
                    ((__nv_bfloat16*)Cm)[cb + o] = __float2bfloat16(val + bias[rowBase + r]);
                } else {  // EPI 2
                    ((float*)Cm)[cb + o] =
                        val * aux[wn0 + j * 16 + c] + xres[strideX * (size_t)b + o];
                }
            }
            __syncwarp();
        }
    }
}

static constexpr size_t pipe_smem(bool AROW, bool BROW) {
    int SA_R = AROW ? 128 : 64, SA_C = AROW ? 64 : 128;
    int SB_R = BROW ? 64 : 128, SB_C = BROW ? 128 : 64;
    return (size_t)3 * (SA_R * (SA_C + 8) + SB_R * (SB_C + 8)) * 2;
}

// ---------------- launch ----------------
extern "C" void kernel_launch(void* const* d_in, const int* in_sizes, int n_in,
                              void* d_out, int out_size) {
    const float* x     = (const float*)d_in[0];
    const float* Wq    = (const float*)d_in[1];
    const float* bq    = (const float*)d_in[2];
    const float* Wk    = (const float*)d_in[3];
    const float* bk    = (const float*)d_in[4];
    const float* Wv    = (const float*)d_in[5];
    const float* bv    = (const float*)d_in[6];
    const float* gamma = (const float*)d_in[7];

    __nv_bfloat16 *xb, *wqk, *wv, *qk, *v, *attn;
    float *bqk, *rspart;
    cudaGetSymbolAddress((void**)&xb, g_xb);
    cudaGetSymbolAddress((void**)&wqk, g_Wqk);
    cudaGetSymbolAddress((void**)&bqk, g_bqk);
    cudaGetSymbolAddress((void**)&wv, g_Wv);
    cudaGetSymbolAddress((void**)&qk, g_qk);
    cudaGetSymbolAddress((void**)&v, g_v);
    cudaGetSymbolAddress((void**)&attn, g_attn);
    cudaGetSymbolAddress((void**)&rspart, g_rspart);

    const size_t sX = (size_t)CCH * NPIX;
    const size_t sQK = (size_t)2 * CQD * NPIX;
    const size_t sS = (size_t)NPIX * NPIX;

    // casts + bias concat
    {
        size_t n4 = (size_t)BATCH * sX / 4;
        cast_kernel<<<(unsigned)((n4 + 255) / 256), 256>>>(x, xb, n4);
        size_t nq4 = (size_t)CQD * CCH / 4;
        cast_kernel<<<(unsigned)((nq4 + 255) / 256), 256>>>(Wq, wqk, nq4);
        cast_kernel<<<(unsigned)((nq4 + 255) / 256), 256>>>(Wk, wqk + CQD * CCH, nq4);
        size_t nv4 = (size_t)CCH * CCH / 4;
        cast_kernel<<<(unsigned)((nv4 + 255) / 256), 256>>>(Wv, wv, nv4);
        concat_bias<<<1, 128>>>(bq, bk, bqk);
    }

    // [q;k] = [Wq;Wk] @ xb + [bq;bk]   one M=128 GEMM per batch, bf16 out
    {
        auto kfn = gemm_pipe<true, true, 1>;
        size_t sm = pipe_smem(true, true);
        cudaFuncSetAttribute(kfn, cudaFuncAttributeMaxDynamicSharedMemorySize, (int)sm);
        dim3 g(NPIX / 128, 1, BATCH);
        kfn<<<g, 128, sm>>>(wqk, 0, CCH, xb, sX, NPIX, qk, sQK, NPIX, bqk,
                            nullptr, nullptr, 0, nullptr, 2 * CQD, NPIX, CCH);
    }

    // v = Wv @ xb + bv   [512 x 4096] per batch, bf16 out
    {
        auto kfn = gemm_pipe<true, true, 1>;
        size_t sm = pipe_smem(true, true);
        cudaFuncSetAttribute(kfn, cudaFuncAttributeMaxDynamicSharedMemorySize, (int)sm);
        dim3 g(NPIX / 128, CCH / 128, BATCH);
        kfn<<<g, 128, sm>>>(wv, 0, CCH, xb, sX, NPIX, v, sX, NPIX, bv,
                            nullptr, nullptr, 0, nullptr, CCH, NPIX, CCH);
    }

    // attn = exp(q^T k) with register-fused partial rowsums (8 j-tiles per CTA)
    {
        cudaFuncSetAttribute(scores_pipe,
                             cudaFuncAttributeMaxDynamicSharedMemorySize, (int)SCORES_SMEM);
        dim3 g(4, NPIX / 128, BATCH);
        scores_pipe<<<g, 128, SCORES_SMEM>>>(qk, attn, rspart);
    }

    // out[c,i] = gamma/rowsum[i] * sum_j v[c,j]*attn[i,j] + x[c,i]  -> fp32
    // (rowsum = sum of 4 rspart groups, folded into the epilogue)
    {
        auto kfn = gemm_pipe<true, false, 2>;
        size_t sm = pipe_smem(true, false);
        cudaFuncSetAttribute(kfn, cudaFuncAttributeMaxDynamicSharedMemorySize, (int)sm);
        dim3 g(NPIX / 128, CCH / 128, BATCH);
        kfn<<<g, 128, sm>>>(v, sX, NPIX, attn, sS, NPIX, d_out, sX, NPIX, nullptr,
                            gamma, x, sX, rspart, CCH, NPIX, NPIX);
    }
}

// round 17
// speedup vs baseline: 1.0280x; 1.0280x over previous

#include <cuda_runtime.h>
#include <cuda_bf16.h>
#include <mma.h>
#include <cstdint>
#include <cstddef>
#include <type_traits>

using namespace nvcuda;

#define BATCH 8
#define CCH   512
#define NPIX  4096
#define CQD   64

// ---------------- static scratch (no runtime allocation allowed) ----------------
__device__ __nv_bfloat16 g_xb[(size_t)BATCH * CCH * NPIX];       // x in bf16
__device__ __nv_bfloat16 g_Wqk[2 * CQD * CCH];                   // [Wq; Wk]
__device__ float         g_bqk[2 * CQD];                         // [bq; bk]
__device__ __nv_bfloat16 g_Wv[CCH * CCH];
__device__ __nv_bfloat16 g_qk[(size_t)BATCH * 2 * CQD * NPIX];   // q rows 0-63, k rows 64-127
__device__ __nv_bfloat16 g_v[(size_t)BATCH * CCH * NPIX];
__device__ __nv_bfloat16 g_attn[(size_t)BATCH * NPIX * NPIX];    // exp(scores), unnormalized
__device__ float         g_rspart[(size_t)BATCH * 4 * NPIX];     // per-jgroup rowsum partials

// ---------------- helpers ----------------
__device__ __forceinline__ uint32_t smem_u32(const void* p) {
    uint32_t a;
    asm("{ .reg .u64 t; cvta.to.shared.u64 t, %1; cvt.u32.u64 %0, t; }" : "=r"(a) : "l"(p));
    return a;
}
__device__ __forceinline__ void cpa16(uint32_t dst, const void* src) {
    asm volatile("cp.async.cg.shared.global [%0], [%1], 16;" :: "r"(dst), "l"(src));
}
#define CP_COMMIT() asm volatile("cp.async.commit_group;" ::: "memory")
#define CP_WAIT(n)  asm volatile("cp.async.wait_group %0;" :: "n"(n) : "memory")

// ---------------- fp32 -> bf16 cast (vectorized) ----------------
__global__ void cast_kernel(const float* __restrict__ in,
                            __nv_bfloat16* __restrict__ out, size_t n4) {
    size_t i = (size_t)blockIdx.x * blockDim.x + threadIdx.x;
    if (i < n4) {
        float4 f = reinterpret_cast<const float4*>(in)[i];
        __nv_bfloat162 a = __floats2bfloat162_rn(f.x, f.y);
        __nv_bfloat162 b = __floats2bfloat162_rn(f.z, f.w);
        uint2 u;
        u.x = *reinterpret_cast<unsigned*>(&a);
        u.y = *reinterpret_cast<unsigned*>(&b);
        reinterpret_cast<uint2*>(out)[i] = u;
    }
}

// ---------------- bias concat ----------------
__global__ void concat_bias(const float* __restrict__ bq, const float* __restrict__ bk,
                            float* __restrict__ bqk) {
    int t = threadIdx.x;
    bqk[t] = (t < CQD) ? bq[t] : bk[t - CQD];
}

// ============ scores kernel: Q-resident, 8 pipelined j-tiles, register rowsum ============
// attn[i,j] = exp(sum_d q[d,i]*k[d,j]).  128 threads, 4 warps of 64x64.
// Each CTA covers 128 i-rows x 1024 j-cols (jg in 0..3).
__global__ void __launch_bounds__(128, 2)
scores_pipe(const __nv_bfloat16* __restrict__ qk,
            __nv_bfloat16* __restrict__ attn, float* __restrict__ rspart)
{
    constexpr int LDS = 136;                 // 128 + 8 pad (halves)
    constexpr int TILE = 64 * LDS;
    extern __shared__ char dsm[];
    __nv_bfloat16* smA = reinterpret_cast<__nv_bfloat16*>(dsm);     // [64][136]
    __nv_bfloat16* smB = smA + TILE;                                // 2 x [64][136]
    float* stage = reinterpret_cast<float*>(smB + 2 * TILE);        // [4][256]
    float* auxRS = stage + 4 * 256;                                 // [2][128]
    const uint32_t smA_u = smem_u32(smA);
    const uint32_t smB_u = smem_u32(smB);

    const int b = blockIdx.z;
    const int jg = blockIdx.x;               // 0..3, j in [jg*1024, jg*1024+1024)
    const int i0 = blockIdx.y * 128;
    const int tid = threadIdx.x;
    const int wid = tid >> 5, lane = tid & 31;
    const int wm0 = (wid & 1) * 64;
    const int wn0 = (wid >> 1) * 64;

    const __nv_bfloat16* qb = qk + (size_t)b * (2 * CQD) * NPIX;
    const __nv_bfloat16* kb = qb + (size_t)CQD * NPIX;
    __nv_bfloat16* attnb = attn + (size_t)b * NPIX * NPIX;

    float part[4][4];
#pragma unroll
    for (int i = 0; i < 4; i++)
#pragma unroll
        for (int p = 0; p < 4; p++) part[i][p] = 0.0f;

    // prologue: A (q block, resident) + B(j-tile 0)
#pragma unroll
    for (int it = 0; it < 8; ++it) {
        int idx = tid + it * 128;
        int r = idx >> 4, cv = idx & 15;
        cpa16(smA_u + (uint32_t)(r * LDS + cv * 8) * 2,
              qb + (size_t)r * NPIX + i0 + cv * 8);
    }
    {
        const int j0 = jg * 1024;
#pragma unroll
        for (int it = 0; it < 8; ++it) {
            int idx = tid + it * 128;
            int r = idx >> 4, cv = idx & 15;
            cpa16(smB_u + (uint32_t)(r * LDS + cv * 8) * 2,
                  kb + (size_t)r * NPIX + j0 + cv * 8);
        }
    }
    CP_COMMIT();

    for (int jt = 0; jt < 8; ++jt) {
        const int cur = jt & 1;
        if (jt + 1 < 8) {
            const int j0 = jg * 1024 + (jt + 1) * 128;
            const uint32_t bbuf = smB_u + (uint32_t)((cur ^ 1) * TILE) * 2;
#pragma unroll
            for (int it = 0; it < 8; ++it) {
                int idx = tid + it * 128;
                int r = idx >> 4, cv = idx & 15;
                cpa16(bbuf + (uint32_t)(r * LDS + cv * 8) * 2,
                      kb + (size_t)r * NPIX + j0 + cv * 8);
            }
            CP_COMMIT();
            CP_WAIT(1);
        } else {
            CP_WAIT(0);
        }
        __syncthreads();

        // MMA: S(128x128) = A^T * B over K=64
        wmma::fragment<wmma::accumulator, 16, 16, 16, float> acc[4][4];
#pragma unroll
        for (int i = 0; i < 4; i++)
#pragma unroll
            for (int j = 0; j < 4; j++) wmma::fill_fragment(acc[i][j], 0.0f);

        const __nv_bfloat16* b0 = smB + cur * TILE;
#pragma unroll
        for (int kk = 0; kk < 64; kk += 16) {
            wmma::fragment<wmma::matrix_a, 16, 16, 16, __nv_bfloat16, wmma::col_major> af[4];
            wmma::fragment<wmma::matrix_b, 16, 16, 16, __nv_bfloat16, wmma::row_major> bfr[4];
#pragma unroll
            for (int i = 0; i < 4; i++)
                wmma::load_matrix_sync(af[i], smA + kk * LDS + wm0 + i * 16, LDS);
#pragma unroll
            for (int j = 0; j < 4; j++)
                wmma::load_matrix_sync(bfr[j], b0 + kk * LDS + wn0 + j * 16, LDS);
#pragma unroll
            for (int i = 0; i < 4; i++)
#pragma unroll
                for (int j = 0; j < 4; j++)
                    wmma::mma_sync(acc[i][j], af[i], bfr[j], acc[i][j]);
        }
        __syncthreads();

        // epilogue: exp -> attn (bf16x2 stores), register rowsum partials
        const int jbase = jg * 1024 + jt * 128;
#pragma unroll
        for (int i = 0; i < 4; i++) {
#pragma unroll
            for (int j = 0; j < 4; j++) {
                wmma::store_matrix_sync(&stage[wid * 256], acc[i][j], 16, wmma::mem_row_major);
                __syncwarp();
                int rowBase = i0 + wm0 + i * 16;
                int colBase = jbase + wn0 + j * 16;
#pragma unroll
                for (int p = 0; p < 4; ++p) {
                    int pi = lane + 32 * p;          // pair index 0..127
                    int r = pi >> 3, c = (pi & 7) * 2;
                    float e0 = __expf(stage[wid * 256 + r * 16 + c]);
                    float e1 = __expf(stage[wid * 256 + r * 16 + c + 1]);
                    part[i][p] += e0 + e1;
                    __nv_bfloat162 h = __floats2bfloat162_rn(e0, e1);
                    *reinterpret_cast<uint32_t*>(
                        &attnb[(size_t)(rowBase + r) * NPIX + colBase + c]) =
                        *reinterpret_cast<uint32_t*>(&h);
                }
                __syncwarp();
            }
        }
        __syncthreads();
    }

    // end-of-kernel rowsum reduction: 8-lane groups share a row
#pragma unroll
    for (int i = 0; i < 4; i++) {
#pragma unroll
        for (int p = 0; p < 4; p++) {
            float s = part[i][p];
            s += __shfl_xor_sync(0xffffffffu, s, 1);
            s += __shfl_xor_sync(0xffffffffu, s, 2);
            s += __shfl_xor_sync(0xffffffffu, s, 4);
            if ((lane & 7) == 0)
                auxRS[(wid >> 1) * 128 + wm0 + i * 16 + (lane >> 3) + 4 * p] = s;
        }
    }
    __syncthreads();
    rspart[((size_t)b * 4 + jg) * NPIX + i0 + tid] = auxRS[tid] + auxRS[128 + tid];
}
static constexpr size_t SCORES_SMEM =
    (size_t)3 * 64 * 136 * 2 + 4 * 256 * 4 + 2 * 128 * 4 + 128;

// ============ 2-stage pipelined 128x128 GEMM (round-14 proven core) ============
// EPI 1: bf16 (acc + bias[row])
// EPI 2: fp32 (gamma/rowsum[col]*acc + xres), rowsum = sum of 4 rspart groups
template<bool AROW, bool BROW, int EPI>
__global__ void __launch_bounds__(128, 2)
gemm_pipe(const __nv_bfloat16* __restrict__ A, size_t strideA, int lda,
          const __nv_bfloat16* __restrict__ Bm, size_t strideB, int ldb,
          void* __restrict__ Cm, size_t strideC, int ldc,
          const float* __restrict__ bias,
          const float* __restrict__ gamma,
          const float* __restrict__ xres, size_t strideX,
          const float* __restrict__ rspart,
          int M, int N, int K)
{
    constexpr int BM = 128, BN = 128, BK = 64, WM = 64, WN = 64;
    constexpr int WGM = BM / WM;
    constexpr int MI = WM / 16, NI = WN / 16;
    constexpr int SA_R = AROW ? BM : BK, SA_C = AROW ? BK : BM;
    constexpr int SB_R = BROW ? BK : BN, SB_C = BROW ? BN : BK;
    constexpr int LDA_S = SA_C + 8, LDB_S = SB_C + 8;
    constexpr int AELEM = SA_R * LDA_S;
    constexpr int BELEM = SB_R * LDB_S;
    constexpr int CVA = SA_C / 8, CVB = SB_C / 8;
    constexpr int ITA = (SA_R * CVA) / 128;
    constexpr int ITB = (SB_R * CVB) / 128;

    extern __shared__ char dsm[];
    __nv_bfloat16* smA = reinterpret_cast<__nv_bfloat16*>(dsm);
    __nv_bfloat16* smB = smA + 2 * AELEM;
    float* stage = reinterpret_cast<float*>(smB + 2 * BELEM);
    float* aux = stage + 4 * 256;
    const uint32_t smA_u = smem_u32(smA);
    const uint32_t smB_u = smem_u32(smB);

    const int b = blockIdx.z;
    const __nv_bfloat16* Ab = A + strideA * (size_t)b;
    const __nv_bfloat16* Bb = Bm + strideB * (size_t)b;
    const size_t cb = strideC * (size_t)b;

    const int blockM = blockIdx.y * BM;
    const int blockN = blockIdx.x * BN;
    const int tid = threadIdx.x;
    const int wid = tid >> 5, lane = tid & 31;
    const int wm0 = (wid % WGM) * WM;
    const int wn0 = (wid / WGM) * WN;

    using ALayout = typename std::conditional<AROW, wmma::row_major, wmma::col_major>::type;
    using BLayout = typename std::conditional<BROW, wmma::row_major, wmma::col_major>::type;

    wmma::fragment<wmma::accumulator, 16, 16, 16, float> acc[MI][NI];
#pragma unroll
    for (int i = 0; i < MI; i++)
#pragma unroll
        for (int j = 0; j < NI; j++) wmma::fill_fragment(acc[i][j], 0.0f);

#pragma unroll
    for (int it = 0; it < ITA; ++it) {
        int idx = tid + it * 128;
        int r = idx / CVA, cv = idx % CVA;
        const __nv_bfloat16* src = AROW
            ? Ab + (size_t)(blockM + r) * lda + cv * 8
            : Ab + (size_t)r * lda + blockM + cv * 8;
        cpa16(smA_u + (uint32_t)(r * LDA_S + cv * 8) * 2, src);
    }
#pragma unroll
    for (int it = 0; it < ITB; ++it) {
        int idx = tid + it * 128;
        int r = idx / CVB, cv = idx % CVB;
        const __nv_bfloat16* src = BROW
            ? Bb + (size_t)r * ldb + blockN + cv * 8
            : Bb + (size_t)(blockN + r) * ldb + cv * 8;
        cpa16(smB_u + (uint32_t)(r * LDB_S + cv * 8) * 2, src);
    }
    CP_COMMIT();

    const int T = K / BK;
    for (int t = 0; t < T; ++t) {
        const int cur = t & 1;
        if (t + 1 < T) {
            const int k0 = (t + 1) * BK;
            const uint32_t abuf = smA_u + (uint32_t)((cur ^ 1) * AELEM) * 2;
            const uint32_t bbuf = smB_u + (uint32_t)((cur ^ 1) * BELEM) * 2;
#pragma unroll
            for (int it = 0; it < ITA; ++it) {
                int idx = tid + it * 128;
                int r = idx / CVA, cv = idx % CVA;
                const __nv_bfloat16* src = AROW
                    ? Ab + (size_t)(blockM + r) * lda + k0 + cv * 8
                    : Ab + (size_t)(k0 + r) * lda + blockM + cv * 8;
                cpa16(abuf + (uint32_t)(r * LDA_S + cv * 8) * 2, src);
            }
#pragma unroll
            for (int it = 0; it < ITB; ++it) {
                int idx = tid + it * 128;
                int r = idx / CVB, cv = idx % CVB;
                const __nv_bfloat16* src = BROW
                    ? Bb + (size_t)(k0 + r) * ldb + blockN + cv * 8
                    : Bb + (size_t)(blockN + r) * ldb + k0 + cv * 8;
                cpa16(bbuf + (uint32_t)(r * LDB_S + cv * 8) * 2, src);
            }
            CP_COMMIT();
            CP_WAIT(1);
        } else {
            CP_WAIT(0);
        }
        __syncthreads();

        const __nv_bfloat16* a0 = smA + cur * AELEM;
        const __nv_bfloat16* b0 = smB + cur * BELEM;
#pragma unroll
        for (int kk = 0; kk < BK; kk += 16) {
            wmma::fragment<wmma::matrix_a, 16, 16, 16, __nv_bfloat16, ALayout> af[MI];
            wmma::fragment<wmma::matrix_b, 16, 16, 16, __nv_bfloat16, BLayout> bfr[NI];
#pragma unroll
            for (int i = 0; i < MI; i++) {
                const __nv_bfloat16* p = AROW ? a0 + (wm0 + i * 16) * LDA_S + kk
                                              : a0 + kk * LDA_S + wm0 + i * 16;
                wmma::load_matrix_sync(af[i], p, LDA_S);
            }
#pragma unroll
            for (int j = 0; j < NI; j++) {
                const __nv_bfloat16* p = BROW ? b0 + kk * LDB_S + wn0 + j * 16
                                              : b0 + (wn0 + j * 16) * LDB_S + kk;
                wmma::load_matrix_sync(bfr[j], p, LDB_S);
            }
#pragma unroll
            for (int i = 0; i < MI; i++)
#pragma unroll
                for (int j = 0; j < NI; j++)
                    wmma::mma_sync(acc[i][j], af[i], bfr[j], acc[i][j]);
        }
        __syncthreads();
    }

    if (EPI == 2) {
        float rs = 0.0f;
#pragma unroll
        for (int jg = 0; jg < 4; ++jg)
            rs += rspart[((size_t)b * 4 + jg) * NPIX + blockN + tid];
        aux[tid] = gamma[0] / rs;
        __syncthreads();
    }

#pragma unroll
    for (int i = 0; i < MI; i++) {
#pragma unroll
        for (int j = 0; j < NI; j++) {
            wmma::store_matrix_sync(&stage[wid * 256], acc[i][j], 16, wmma::mem_row_major);
            __syncwarp();
            int rowBase = blockM + wm0 + i * 16;
            int colBase = blockN + wn0 + j * 16;
#pragma unroll
            for (int e = lane; e < 256; e += 32) {
                int r = e >> 4, c = e & 15;
                float val = stage[wid * 256 + e];
                size_t o = (size_t)(rowBase + r) * ldc + colBase + c;
                if (EPI == 1) {
                    ((__nv_bfloat16*)Cm)[cb + o] = __float2bfloat16(val + bias[rowBase + r]);
                } else {  // EPI 2
                    ((float*)Cm)[cb + o] =
                        val * aux[wn0 + j * 16 + c] + xres[strideX * (size_t)b + o];
                }
            }
            __syncwarp();
        }
    }
}

static constexpr size_t pipe_smem(bool AROW, bool BROW) {
    int SA_R = AROW ? 128 : 64, SA_C = AROW ? 64 : 128;
    int SB_R = BROW ? 64 : 128, SB_C = BROW ? 128 : 64;
    return (size_t)2 * (SA_R * (SA_C + 8) + SB_R * (SB_C + 8)) * 2 +
           (size_t)4 * 256 * 4 + 512;
}

// ---------------- launch ----------------
extern "C" void kernel_launch(void* const* d_in, const int* in_sizes, int n_in,
                              void* d_out, int out_size) {
    const float* x     = (const float*)d_in[0];
    const float* Wq    = (const float*)d_in[1];
    const float* bq    = (const float*)d_in[2];
    const float* Wk    = (const float*)d_in[3];
    const float* bk    = (const float*)d_in[4];
    const float* Wv    = (const float*)d_in[5];
    const float* bv    = (const float*)d_in[6];
    const float* gamma = (const float*)d_in[7];

    __nv_bfloat16 *xb, *wqk, *wv, *qk, *v, *attn;
    float *bqk, *rspart;
    cudaGetSymbolAddress((void**)&xb, g_xb);
    cudaGetSymbolAddress((void**)&wqk, g_Wqk);
    cudaGetSymbolAddress((void**)&bqk, g_bqk);
    cudaGetSymbolAddress((void**)&wv, g_Wv);
    cudaGetSymbolAddress((void**)&qk, g_qk);
    cudaGetSymbolAddress((void**)&v, g_v);
    cudaGetSymbolAddress((void**)&attn, g_attn);
    cudaGetSymbolAddress((void**)&rspart, g_rspart);

    const size_t sX = (size_t)CCH * NPIX;
    const size_t sQK = (size_t)2 * CQD * NPIX;
    const size_t sS = (size_t)NPIX * NPIX;

    // casts + bias concat
    {
        size_t n4 = (size_t)BATCH * sX / 4;
        cast_kernel<<<(unsigned)((n4 + 255) / 256), 256>>>(x, xb, n4);
        size_t nq4 = (size_t)CQD * CCH / 4;
        cast_kernel<<<(unsigned)((nq4 + 255) / 256), 256>>>(Wq, wqk, nq4);
        cast_kernel<<<(unsigned)((nq4 + 255) / 256), 256>>>(Wk, wqk + CQD * CCH, nq4);
        size_t nv4 = (size_t)CCH * CCH / 4;
        cast_kernel<<<(unsigned)((nv4 + 255) / 256), 256>>>(Wv, wv, nv4);
        concat_bias<<<1, 128>>>(bq, bk, bqk);
    }

    // [q;k] = [Wq;Wk] @ xb + [bq;bk]   one M=128 GEMM per batch, bf16 out
    {
        auto kfn = gemm_pipe<true, true, 1>;
        size_t sm = pipe_smem(true, true);
        cudaFuncSetAttribute(kfn, cudaFuncAttributeMaxDynamicSharedMemorySize, (int)sm);
        dim3 g(NPIX / 128, 1, BATCH);
        kfn<<<g, 128, sm>>>(wqk, 0, CCH, xb, sX, NPIX, qk, sQK, NPIX, bqk,
                            nullptr, nullptr, 0, nullptr, 2 * CQD, NPIX, CCH);
    }

    // v = Wv @ xb + bv   [512 x 4096] per batch, bf16 out
    {
        auto kfn = gemm_pipe<true, true, 1>;
        size_t sm = pipe_smem(true, true);
        cudaFuncSetAttribute(kfn, cudaFuncAttributeMaxDynamicSharedMemorySize, (int)sm);
        dim3 g(NPIX / 128, CCH / 128, BATCH);
        kfn<<<g, 128, sm>>>(wv, 0, CCH, xb, sX, NPIX, v, sX, NPIX, bv,
                            nullptr, nullptr, 0, nullptr, CCH, NPIX, CCH);
    }

    // attn = exp(q^T k) with register-fused partial rowsums (8 j-tiles per CTA)
    {
        cudaFuncSetAttribute(scores_pipe,
                             cudaFuncAttributeMaxDynamicSharedMemorySize, (int)SCORES_SMEM);
        dim3 g(4, NPIX / 128, BATCH);
        scores_pipe<<<g, 128, SCORES_SMEM>>>(qk, attn, rspart);
    }

    // out[c,i] = gamma/rowsum[i] * sum_j v[c,j]*attn[i,j] + x[c,i]  -> fp32
    // (rowsum = sum of 4 rspart groups, folded into the epilogue)
    {
        auto kfn = gemm_pipe<true, false, 2>;
        size_t sm = pipe_smem(true, false);
        cudaFuncSetAttribute(kfn, cudaFuncAttributeMaxDynamicSharedMemorySize, (int)sm);
        dim3 g(NPIX / 128, CCH / 128, BATCH);
        kfn<<<g, 128, sm>>>(v, sX, NPIX, attn, sS, NPIX, d_out, sX, NPIX, nullptr,
                            gamma, x, sX, rspart, CCH, NPIX, NPIX);
    }
}